// round 10
// baseline (speedup 1.0000x reference)
#include <cuda_runtime.h>

#define H1   1000
#define NCH1 1400     // layer-1 row chunks
#define RPC1 24       // rows per chunk (1400*24 = 33600)

#define NS   307      // needed layer-2 columns (x2[15k+1])
#define KC2  40       // layer-2 k chunks
#define RPC2 25       // rows per chunk (40*25 = 1000)

// ---------------- scratch (__device__ globals; no allocations) ----------------
__device__ float g_part1[NCH1 * H1];         // layer-1 partial sums [chunk][j]
__device__ float g_part2[KC2 * 320];         // layer-2 partials for the 307 scalars

// ---------------- layer 1: partial GEMV, 1400 blocks x 256 thr ---------------
// Explicit 8-deep load batching: 8 LDG.128 issued back-to-back -> MLP ~8.
__global__ void __launch_bounds__(256) k_l1_partial(const float* __restrict__ x,
                                                    const float* __restrict__ W) {
    __shared__ float xs[RPC1];
    int bx = blockIdx.x, tid = threadIdx.x;
    int i0 = bx * RPC1;
    if (tid < RPC1) xs[tid] = x[i0 + tid];
    __syncthreads();
    if (tid < 250) {
        const float4* W4 = (const float4*)W;   // 1000 floats/row = 250 float4
        const float4* p = &W4[(size_t)i0 * 250 + tid];
        float4 a = make_float4(0.f, 0.f, 0.f, 0.f);
        #pragma unroll
        for (int b = 0; b < 3; ++b) {
            float4 w[8];
            #pragma unroll
            for (int r = 0; r < 8; ++r)
                w[r] = __ldcs(p + (size_t)(b * 8 + r) * 250);
            #pragma unroll
            for (int r = 0; r < 8; ++r) {
                float xv = xs[b * 8 + r];
                a.x = fmaf(xv, w[r].x, a.x);
                a.y = fmaf(xv, w[r].y, a.y);
                a.z = fmaf(xv, w[r].z, a.z);
                a.w = fmaf(xv, w[r].w, a.w);
            }
        }
        ((float4*)g_part1)[bx * 250 + tid] = a;
    }
}

// -------- mid: fold layer-1 partials -> h1 (shared), then layer-2 partials ---
// 40 blocks x 512 threads; block bx owns h1 rows [bx*25, bx*25+25)
__global__ void __launch_bounds__(512) k_mid(const float* __restrict__ bd1,
                                             const float* __restrict__ Wd2) {
    __shared__ float red[350];
    __shared__ float hs[RPC2];
    int tid = threadIdx.x, bx = blockIdx.x;
    int i0 = bx * RPC2;

    if (tid < 350) {                           // 25 rows x 14 chunk-groups
        int jj = tid % 25, g = tid / 25;
        float v = 0.f;
        int c0 = g * 100;                      // 1400/14
        #pragma unroll 10
        for (int c = 0; c < 100; ++c)
            v += g_part1[(c0 + c) * H1 + i0 + jj];
        red[tid] = v;
    }
    __syncthreads();
    if (tid < RPC2) {
        float s = bd1[i0 + tid];
        #pragma unroll
        for (int g = 0; g < 14; ++g) s += red[g * 25 + tid];
        hs[tid] = fmaxf(s, 0.f);
    }
    __syncthreads();
    if (tid < NS) {
        float acc = 0.f;
        const float* base = Wd2 + (size_t)i0 * 4605 + 15 * tid + 1;
        #pragma unroll
        for (int r = 0; r < RPC2; ++r)
            acc = fmaf(hs[r], base[(size_t)r * 4605], acc);
        g_part2[bx * 320 + tid] = acc;
    }
}

// ---------------- shared helpers ---------------------------------------------
__device__ __forceinline__ void fold_scalars(float* s_sh, const float* __restrict__ bd2,
                                             int sbase, int JB) {
    int tid = threadIdx.x;
    if (tid < JB) {
        int ks = sbase + tid;
        float v = bd2[15 * ks + 1];
        #pragma unroll
        for (int c = 0; c < KC2; ++c) v += g_part2[c * 320 + ks];
        s_sh[tid] = fmaxf(v, 0.f);
    }
}

// ---- seg1: 16 x 500 x 5121. warp-split-k, smem reduce, direct final write ---
// smem partition: s[0:16], h[16:16+8064] (504 rows x 16), red[8080:8080+4096]
__device__ __forceinline__ void seg1_body(
    float* smem, float* __restrict__ out, const float* __restrict__ bd2,
    const float* __restrict__ Wa, const float* __restrict__ ba,
    const float* __restrict__ Wb, const float* __restrict__ bb, int blk)
{
    const int O = 5121;
    float* s_sh = smem;
    float* h_sh = smem + 16;
    float* red  = smem + 8080;
    int tid = threadIdx.x;

    fold_scalars(s_sh, bd2, 0, 16);
    __syncthreads();

    // hidden: h[k][j] for k in [0,504), zero-padded beyond 500
    #pragma unroll
    for (int k = tid; k < 504; k += 256) {
        float av = 0.f, bv = 0.f;
        if (k < 500) { av = Wa[k]; bv = ba[k]; }
        float* hk = &h_sh[k * 16];
        #pragma unroll
        for (int j = 0; j < 16; ++j) {
            float v = (k < 500) ? fmaxf(fmaf(s_sh[j], av, bv), 0.f) : 0.f;
            hk[j] = v;
        }
    }
    __syncthreads();

    int w = tid >> 5, lane = tid & 31;
    int n = blk * 32 + lane;
    bool nok = (n < O);
    int k0 = w * 63;

    float acc[16];
    #pragma unroll
    for (int j = 0; j < 16; ++j) acc[j] = 0.f;

    #pragma unroll 21
    for (int r = 0; r < 63; ++r) {
        int k = k0 + r;
        float wv = (nok && k < 500) ? Wb[(size_t)k * O + n] : 0.f;
        const float* hr = &h_sh[k * 16];
        #pragma unroll
        for (int j = 0; j < 16; ++j)
            acc[j] = fmaf(hr[j], wv, acc[j]);
    }

    // reduce 8 warps in shared: red[w][j][lane]
    #pragma unroll
    for (int j = 0; j < 16; ++j)
        red[w * 512 + j * 32 + lane] = acc[j];
    __syncthreads();

    #pragma unroll
    for (int p = tid; p < 512; p += 256) {
        int j = p >> 5, ln = p & 31;
        int nn = blk * 32 + ln;
        if (nn < O) {
            float v = bb[nn];
            #pragma unroll
            for (int ww = 0; ww < 8; ++ww) v += red[ww * 512 + p];
            out[(size_t)j * O + nn] = fmaxf(v, 0.f);
        }
    }
}

// ---- direct segment: JB scalars x (256*CPT) cols, full K=100, final write ---
template<int JB, int CPT>
__device__ __forceinline__ void seg_direct(
    float* smem, float* __restrict__ out, const float* __restrict__ bd2,
    const float* __restrict__ Wa, const float* __restrict__ ba,
    const float* __restrict__ Wb, const float* __restrict__ bb,
    int O, int sbase, int jg0, int ct)
{
    float* s_sh = smem;
    float* h_sh = smem + 16;                   // [k][JB], 100*JB <= 400
    int tid = threadIdx.x;

    fold_scalars(s_sh, bd2, sbase + jg0, JB);
    __syncthreads();

    if (tid < 100) {
        float av = Wa[tid], bv = ba[tid];
        float* hk = &h_sh[tid * JB];
        #pragma unroll
        for (int j = 0; j < JB; ++j)
            hk[j] = fmaxf(fmaf(s_sh[j], av, bv), 0.f);
    }
    __syncthreads();

    int nb = ct * (256 * CPT) + tid;
    float acc[JB * CPT];
    #pragma unroll
    for (int i = 0; i < JB * CPT; ++i) acc[i] = 0.f;

    #pragma unroll 20
    for (int r = 0; r < 100; ++r) {
        const float* wrow = Wb + (size_t)r * O;
        float w[CPT];
        #pragma unroll
        for (int c = 0; c < CPT; ++c) {
            int n = nb + c * 256;
            w[c] = (n < O) ? wrow[n] : 0.f;
        }
        const float* hr = &h_sh[r * JB];
        #pragma unroll
        for (int j = 0; j < JB; ++j) {
            float hv = hr[j];
            #pragma unroll
            for (int c = 0; c < CPT; ++c)
                acc[j * CPT + c] = fmaf(hv, w[c], acc[j * CPT + c]);
        }
    }

    #pragma unroll
    for (int j = 0; j < JB; ++j) {
        #pragma unroll
        for (int c = 0; c < CPT; ++c) {
            int n = nb + c * 256;
            if (n < O)
                out[(size_t)(jg0 + j) * O + n] = fmaxf(acc[j * CPT + c] + bb[n], 0.f);
        }
    }
}

// seg1: 161 blocks (5121/32)   | seg3: 64 blocks (256 j / 4)
// seg2: 8 blocks (32 j / 4)    | seg4: 7 blocks (1542 cols / 256)
__global__ void __launch_bounds__(256) k_segments(
    float* __restrict__ out,
    const float* __restrict__ bd2,
    const float* __restrict__ W1a, const float* __restrict__ b1a, const float* __restrict__ W1b, const float* __restrict__ b1b,
    const float* __restrict__ W2a, const float* __restrict__ b2a, const float* __restrict__ W2b, const float* __restrict__ b2b,
    const float* __restrict__ W3a, const float* __restrict__ b3a, const float* __restrict__ W3b, const float* __restrict__ b3b,
    const float* __restrict__ W4a, const float* __restrict__ b4a, const float* __restrict__ W4b, const float* __restrict__ b4b)
{
    __shared__ float smem[12192];
    int b = blockIdx.x;
    if (b < 161) {
        seg1_body(smem, out, bd2, W1a, b1a, W1b, b1b, b);
    } else if (b < 225) {
        int jb = b - 161;
        seg_direct<4, 2>(smem, out + 90160, bd2, W3a, b3a, W3b, b3b, 321, 48, jb * 4, 0);
    } else if (b < 233) {
        int jb = b - 225;
        seg_direct<4, 2>(smem, out + 81936, bd2, W2a, b2a, W2b, b2b, 257, 16, jb * 4, 0);
    } else {
        int ct = b - 233;
        seg_direct<3, 1>(smem, out + 172336, bd2, W4a, b4a, W4b, b4b, 1542, 304, 0, ct);
    }
}

extern "C" void kernel_launch(void* const* d_in, const int* in_sizes, int n_in,
                              void* d_out, int out_size) {
    const float* x   = (const float*)d_in[0];
    const float* Wd1 = (const float*)d_in[1];
    const float* bd1 = (const float*)d_in[2];
    const float* Wd2 = (const float*)d_in[3];
    const float* bd2 = (const float*)d_in[4];
    const float* W1a = (const float*)d_in[5];
    const float* b1a = (const float*)d_in[6];
    const float* W1b = (const float*)d_in[7];
    const float* b1b = (const float*)d_in[8];
    const float* W2a = (const float*)d_in[9];
    const float* b2a = (const float*)d_in[10];
    const float* W2b = (const float*)d_in[11];
    const float* b2b = (const float*)d_in[12];
    const float* W3a = (const float*)d_in[13];
    const float* b3a = (const float*)d_in[14];
    const float* W3b = (const float*)d_in[15];
    const float* b3b = (const float*)d_in[16];
    const float* W4a = (const float*)d_in[17];
    const float* b4a = (const float*)d_in[18];
    const float* W4b = (const float*)d_in[19];
    const float* b4b = (const float*)d_in[20];
    float* out = (float*)d_out;

    k_l1_partial<<<NCH1, 256>>>(x, Wd1);
    k_mid<<<KC2, 512>>>(bd1, Wd2);
    k_segments<<<240, 256>>>(out, bd2,
                             W1a, b1a, W1b, b1b,
                             W2a, b2a, W2b, b2b,
                             W3a, b3a, W3b, b3b,
                             W4a, b4a, W4b, b4b);
}